// round 16
// baseline (speedup 1.0000x reference)
#include <cuda_runtime.h>
#include <cuda_fp16.h>
#include <cstdint>
#include <cstddef>

#define N_TOKENS 8192
#define NGROUP   32
#define NC       8                      // chunks of 1024 tokens
#define SEGS     30                     // 10 triplets x (K1,K2,K3)
#define ITEMS_SEG 512
#define TOTAL_IDX (SEGS * ITEMS_SEG)

// Scratch (device globals — no runtime allocation).
__device__ uint32_t g_xm2[(size_t)NGROUP * N_TOKENS * 64];   // x_mixed fp16 [g][t][i/2]
__device__ uint32_t g_yp2[(size_t)N_TOKENS * NGROUP * 64];   // y_parts fp16 [t][g][o/2]
__device__ uint32_t g_wf16[(size_t)NGROUP * 128 * 64];       // decoded W fp16 [g][o][k]
__device__ int g_next;
__device__ int g_done1[NC];
__device__ int g_done2[NC];

// ---------------------------------------------------------------------------
__device__ __forceinline__ uint32_t smem_u32(const void* p) {
    uint32_t a;
    asm("{ .reg .u64 t; cvta.to.shared.u64 t, %1; cvt.u32.u64 %0, t; }"
        : "=r"(a) : "l"(p));
    return a;
}
__device__ __forceinline__ void cp16(uint32_t s, const void* g) {
    asm volatile("cp.async.cg.shared.global [%0], [%1], 16;" :: "r"(s), "l"(g));
}
__device__ __forceinline__ void cp16_ef(uint32_t s, const void* g) {
    asm volatile(
        "{\n\t.reg .b64 pol;\n\t"
        "createpolicy.fractional.L2::evict_first.b64 pol;\n\t"
        "cp.async.cg.shared.global.L2::cache_hint [%0], [%1], 16, pol;\n\t}"
        :: "r"(s), "l"(g));
}
__device__ __forceinline__ void ldsm_x4(uint32_t& r0, uint32_t& r1,
                                        uint32_t& r2, uint32_t& r3, uint32_t addr) {
    asm volatile("ldmatrix.sync.aligned.m8n8.x4.shared.b16 {%0,%1,%2,%3}, [%4];"
                 : "=r"(r0), "=r"(r1), "=r"(r2), "=r"(r3) : "r"(addr));
}
__device__ __forceinline__ void mma16816(float* c, const uint32_t* a,
                                         uint32_t b0, uint32_t b1) {
    asm volatile("mma.sync.aligned.m16n8k16.row.col.f32.f16.f16.f32 "
                 "{%0,%1,%2,%3}, {%4,%5,%6,%7}, {%8,%9}, {%0,%1,%2,%3};"
                 : "+f"(c[0]), "+f"(c[1]), "+f"(c[2]), "+f"(c[3])
                 : "r"(a[0]), "r"(a[1]), "r"(a[2]), "r"(a[3]), "r"(b0), "r"(b1));
}

__device__ __forceinline__ void bfly4(float4& a, float4& b) {
    float4 ta = a, tb = b;
    a.x = ta.x + tb.x; a.y = ta.y + tb.y; a.z = ta.z + tb.z; a.w = ta.w + tb.w;
    b.x = ta.x - tb.x; b.y = ta.y - tb.y; b.z = ta.z - tb.z; b.w = ta.w - tb.w;
}
__device__ __forceinline__ void wht8(float4* v) {
#pragma unroll
    for (int s = 1; s < 8; s <<= 1)
#pragma unroll
        for (int e = 0; e < 8; e++)
            if ((e & s) == 0) bfly4(v[e], v[e | s]);
}
__device__ __forceinline__ void wht4(float4* v) {
#pragma unroll
    for (int s = 1; s < 4; s <<= 1)
#pragma unroll
        for (int e = 0; e < 4; e++)
            if ((e & s) == 0) bfly4(v[e], v[e | s]);
}

// ---------------------------------------------------------------------------
// K0: decode weights + reset pipeline counters.
// ---------------------------------------------------------------------------
__global__ void __launch_bounds__(256) k0_decode(const int* __restrict__ wpk) {
    if (blockIdx.x == 0 && blockIdx.y == 0) {
        if (threadIdx.x < NC)                    g_done1[threadIdx.x] = 0;
        else if (threadIdx.x < 2 * NC)           g_done2[threadIdx.x - NC] = 0;
        else if (threadIdx.x == 2 * NC)          g_next = 0;
    }
    const int g    = blockIdx.x;
    const int cb   = blockIdx.y * 2;
    const int o    = threadIdx.x >> 1;
    const int half = threadIdx.x & 1;
    const int* row32 = wpk + ((size_t)g * 128 + o) * 32 + half * 16;
    uint2* dst = (uint2*)(g_wf16 + ((size_t)(g * 128 + o)) * 64 + half * 32);
#pragma unroll
    for (int cc = 0; cc < 2; cc++) {
        int c = cb + cc;
        uint32_t by = (uint32_t)__ldg(row32 + c) & 0xFFu;
        uint32_t bits[4];
#pragma unroll
        for (int j = 0; j < 4; j++) {
            uint32_t v2 = (by >> (6 - 2 * j)) & 3u;
            bits[j] = (v2 == 1u) ? 0u : ((v2 == 2u) ? 0x3C00u : 0xBC00u);
        }
        dst[c] = make_uint2(bits[0] | (bits[1] << 16), bits[2] | (bits[3] << 16));
    }
}

// ---------------------------------------------------------------------------
// Work-item bodies (bit-identical math to the R13 kernels).
// ---------------------------------------------------------------------------
__device__ void k1_work(const float* __restrict__ x, int item, float4* su) {
    const int tid = threadIdx.x;
    const int tl  = tid >> 7;
    const int r   = tid & 127;
    const int t   = item * 2 + tl;
    const int iq  = r & 31;
    {
        const int g1 = r >> 5;
        const float4* xr = (const float4*)(x + (size_t)t * 4096) + g1 * 256 + iq;
        float4 v[8];
#pragma unroll
        for (int g0 = 0; g0 < 8; g0++) v[g0] = __ldcs(xr + g0 * 32);
        wht8(v);
        float4* dst = su + ((tl * 4 + g1) * 8) * 32 + iq;
#pragma unroll
        for (int h0 = 0; h0 < 8; h0++) dst[h0 * 32] = v[h0];
    }
    __syncthreads();
    {
        const int h0a = r >> 5;
        uint2* xm = (uint2*)g_xm2;
#pragma unroll
        for (int k = 0; k < 2; k++) {
            const int h0 = h0a + k * 4;
            float4 v[4];
#pragma unroll
            for (int g1 = 0; g1 < 4; g1++)
                v[g1] = su[((tl * 4 + g1) * 8 + h0) * 32 + iq];
            wht4(v);
#pragma unroll
            for (int h1 = 0; h1 < 4; h1++) {
                __half2 lo = __floats2half2_rn(v[h1].x, v[h1].y);
                __half2 hi = __floats2half2_rn(v[h1].z, v[h1].w);
                xm[((size_t)(h1 * 8 + h0) * N_TOKENS + t) * 32 + iq] =
                    make_uint2(*(uint32_t*)&lo, *(uint32_t*)&hi);
            }
        }
    }
    __syncthreads();                               // smem reuse safety
}

#define SMS 272
#define ABUF (64 * SMS)                // 17408
#define BBUF (128 * SMS)               // 34816
#define PIPE_SMEM (ABUF + BBUF)        // 52224 -> 3 CTAs/SM

__device__ void k2_item(int tt, int g, int chunk, char* smem) {
    const uint32_t sA = smem_u32(smem);
    const uint32_t sB = sA + ABUF;
    const int tid  = threadIdx.x;
    const int wid  = tid >> 5;
    const int lane = tid & 31;

    // B fill first (independent of dependency) — overlaps the spin below.
    {
        const char* srcB = (const char*)(g_wf16 + (size_t)g * 128 * 64);
#pragma unroll
        for (int it = 0; it < 8; it++) {
            int idx = tid + it * 256;
            int rr = idx >> 4, q = idx & 15;
            cp16(sB + rr * SMS + q * 16, srcB + (size_t)rr * 256 + q * 16);
        }
    }
    // Acquire: wait for K1 of this chunk.
    if (tid == 0) {
        while (atomicAdd(&g_done1[chunk], 0) < ITEMS_SEG) __nanosleep(256);
        __threadfence();
    }
    __syncthreads();
    // A fill
    {
        const char* src = (const char*)(g_xm2 + ((size_t)g * N_TOKENS + (size_t)tt * 64) * 64);
#pragma unroll
        for (int it = 0; it < 4; it++) {
            int idx = tid + it * 256;
            int rr = idx >> 4, q = idx & 15;
            cp16_ef(sA + rr * SMS + q * 16, src + (size_t)rr * 256 + q * 16);
        }
    }
    asm volatile("cp.async.commit_group;");
    asm volatile("cp.async.wait_group 0;");
    __syncthreads();

    const int wm = (wid & 1) * 32;
    const int wn = (wid >> 1) * 32;
    const int a_row = (lane & 7) + ((lane >> 3) & 1) * 8;
    const int a_col = ((lane >> 4) & 1) * 16;
    const int b_row = (lane & 7) + ((lane >> 4) & 1) * 8;
    const int b_col = ((lane >> 3) & 1) * 16;
    const uint32_t aLane = sA + (wm + a_row) * SMS + a_col;
    const uint32_t bLane = sB + (wn + b_row) * SMS + b_col;

    float acc[2][4][4];
#pragma unroll
    for (int mt = 0; mt < 2; mt++)
#pragma unroll
        for (int nt = 0; nt < 4; nt++)
#pragma unroll
            for (int q = 0; q < 4; q++) acc[mt][nt][q] = 0.0f;

#pragma unroll
    for (int ks = 0; ks < 8; ks++) {
        uint32_t a[2][4];
#pragma unroll
        for (int mt = 0; mt < 2; mt++)
            ldsm_x4(a[mt][0], a[mt][1], a[mt][2], a[mt][3],
                    aLane + mt * 16 * SMS + ks * 32);
        uint32_t b[2][4];
#pragma unroll
        for (int n2 = 0; n2 < 2; n2++)
            ldsm_x4(b[n2][0], b[n2][1], b[n2][2], b[n2][3],
                    bLane + n2 * 16 * SMS + ks * 32);
#pragma unroll
        for (int mt = 0; mt < 2; mt++)
#pragma unroll
            for (int nt = 0; nt < 4; nt++) {
                uint32_t b0 = b[nt >> 1][(nt & 1) * 2 + 0];
                uint32_t b1 = b[nt >> 1][(nt & 1) * 2 + 1];
                mma16816(acc[mt][nt], a[mt], b0, b1);
            }
    }

    __syncthreads();
    {
        const int rbase = wm + (lane >> 2);
#pragma unroll
        for (int mt = 0; mt < 2; mt++) {
#pragma unroll
            for (int nt = 0; nt < 4; nt++) {
                int colu = (wn >> 1) + nt * 4 + (lane & 3);
                __half2 lo = __floats2half2_rn(acc[mt][nt][0], acc[mt][nt][1]);
                __half2 hi = __floats2half2_rn(acc[mt][nt][2], acc[mt][nt][3]);
                int r0 = rbase + mt * 16;
                *(uint32_t*)(smem + (size_t)r0 * SMS + (size_t)colu * 4) = *(uint32_t*)&lo;
                *(uint32_t*)(smem + (size_t)(r0 + 8) * SMS + (size_t)colu * 4) = *(uint32_t*)&hi;
            }
        }
    }
    __syncthreads();
    {
        uint32_t* ypbase = g_yp2 + ((size_t)tt * 64 * 32 + g) * 64;
#pragma unroll
        for (int it = 0; it < 4; it++) {
            int idx = tid + it * 256;
            int row = idx >> 4, q = idx & 15;
            uint4 v = *(const uint4*)(smem + (size_t)row * SMS + (size_t)q * 16);
            *(uint4*)(ypbase + (size_t)row * 2048 + q * 4) = v;
        }
    }
    __syncthreads();
}

__device__ void k3_work(const float* __restrict__ beta, float* __restrict__ y,
                        int item, float4* su) {
    const int tid = threadIdx.x;
    const int tl  = tid >> 7;
    const int r   = tid & 127;
    const int t   = item * 2 + tl;
    const int oq  = r & 31;
    {
        const int g1 = r >> 5;
        const uint2* yr = (const uint2*)g_yp2 + (size_t)t * 1024 + g1 * 256 + oq;
        float4 v[8];
#pragma unroll
        for (int g0 = 0; g0 < 8; g0++) {
            uint2 pk = __ldcs(yr + g0 * 32);
            float2 a = __half22float2(*(__half2*)&pk.x);
            float2 b = __half22float2(*(__half2*)&pk.y);
            v[g0] = make_float4(a.x, a.y, b.x, b.y);
        }
        wht8(v);
        float4* dst = su + ((tl * 4 + g1) * 8) * 32 + oq;
#pragma unroll
        for (int h0 = 0; h0 < 8; h0++) dst[h0 * 32] = v[h0];
    }
    __syncthreads();
    {
        const int h0a = r >> 5;
        const float4 bb = __ldg((const float4*)beta + oq);
        const float s0 = bb.x * (1.0f / 32.0f), s1 = bb.y * (1.0f / 32.0f);
        const float s2 = bb.z * (1.0f / 32.0f), s3 = bb.w * (1.0f / 32.0f);
        float4* out = (float4*)(y + (size_t)t * 4096) + oq;
#pragma unroll
        for (int k = 0; k < 2; k++) {
            const int h0 = h0a + k * 4;
            float4 v[4];
#pragma unroll
            for (int g1 = 0; g1 < 4; g1++)
                v[g1] = su[((tl * 4 + g1) * 8 + h0) * 32 + oq];
            wht4(v);
#pragma unroll
            for (int h1 = 0; h1 < 4; h1++) {
                float4 o;
                o.x = v[h1].x * s0; o.y = v[h1].y * s1;
                o.z = v[h1].z * s2; o.w = v[h1].w * s3;
                __stcs(out + (h1 * 8 + h0) * 32, o);
            }
        }
    }
    __syncthreads();
}

// ---------------------------------------------------------------------------
// Persistent dynamic-queue pipeline: 444 CTAs (3/SM, one wave, deadlock-free).
// Schedule: 30 segments of 512 items; triplet t -> (K1 chunk t | K2 t-1 | K3 t-2),
// out-of-range segments are no-op pops. Dependencies via done-counters.
// ---------------------------------------------------------------------------
__global__ void __launch_bounds__(256, 3) k_pipeline(const float* __restrict__ x,
                                                     const float* __restrict__ beta,
                                                     float* __restrict__ y) {
    extern __shared__ char smem[];
    float4* su = (float4*)smem;
    __shared__ int s_idx;

    for (;;) {
        if (threadIdx.x == 0) s_idx = atomicAdd(&g_next, 1);
        __syncthreads();
        const int idx = s_idx;
        __syncthreads();                            // protect s_idx before next pop
        if (idx >= TOTAL_IDX) break;

        const int seg  = idx >> 9;
        const int sub  = idx & 511;
        const int tri  = seg / 3;
        const int kind = seg - tri * 3;             // 0:K1 1:K2 2:K3
        const int chunk = tri - kind;
        if (chunk < 0 || chunk >= NC) continue;

        if (kind == 0) {
            k1_work(x, chunk * ITEMS_SEG + sub, su);
            __threadfence();
            __syncthreads();
            if (threadIdx.x == 0) atomicAdd(&g_done1[chunk], 1);
        } else if (kind == 1) {
            const int g  = sub >> 4;
            const int tt = chunk * 16 + (sub & 15);
            k2_item(tt, g, chunk, smem);
            __threadfence();
            __syncthreads();
            if (threadIdx.x == 0) atomicAdd(&g_done2[chunk], 1);
        } else {
            if (threadIdx.x == 0) {
                while (atomicAdd(&g_done2[chunk], 0) < ITEMS_SEG) __nanosleep(256);
                __threadfence();
            }
            __syncthreads();
            k3_work(beta, y, chunk * ITEMS_SEG + sub, su);
        }
    }
}

// ---------------------------------------------------------------------------
extern "C" void kernel_launch(void* const* d_in, const int* in_sizes, int n_in,
                              void* d_out, int out_size) {
    const float* x    = nullptr;
    const int*   wp   = nullptr;
    const float* beta = nullptr;

    for (int i = 0; i < n_in; i++) {
        switch (in_sizes[i]) {
            case 33554432: x    = (const float*)d_in[i]; break;
            case 131072:   wp   = (const int*)d_in[i];   break;
            case 128:      beta = (const float*)d_in[i]; break;
            default: break;   // H (1024) ignored
        }
    }
    if (!x)    x    = (const float*)d_in[0];
    if (!wp)   wp   = (const int*)d_in[1];
    if (!beta) beta = (const float*)d_in[2];

    float* y = (float*)d_out;

    cudaFuncSetAttribute(k_pipeline, cudaFuncAttributeMaxDynamicSharedMemorySize, PIPE_SMEM);

    k0_decode<<<dim3(NGROUP, 8), 256>>>(wp);
    k_pipeline<<<444, 256, PIPE_SMEM>>>(x, beta, y);
}

// round 17
// speedup vs baseline: 1.3978x; 1.3978x over previous
#include <cuda_runtime.h>
#include <cuda_fp16.h>
#include <cstdint>
#include <cstddef>

#define N_TOKENS 8192
#define NGROUP   32

// Scratch (device globals — no runtime allocation).
__device__ uint32_t g_xm2[(size_t)NGROUP * N_TOKENS * 64];   // x_mixed fp16 [g][t][i/2]
__device__ uint32_t g_yp2[(size_t)N_TOKENS * NGROUP * 64];   // y_parts fp16 [t][g][o/2]
__device__ uint32_t g_wf16[(size_t)NGROUP * 128 * 64];       // decoded W fp16 [g][o][k]

// ---------------------------------------------------------------------------
__device__ __forceinline__ uint32_t smem_u32(const void* p) {
    uint32_t a;
    asm("{ .reg .u64 t; cvta.to.shared.u64 t, %1; cvt.u32.u64 %0, t; }"
        : "=r"(a) : "l"(p));
    return a;
}
__device__ __forceinline__ void cp16(uint32_t s, const void* g) {
    asm volatile("cp.async.cg.shared.global [%0], [%1], 16;" :: "r"(s), "l"(g));
}
// cp.async with L2 evict-first hint (src data is dead after this read)
__device__ __forceinline__ void cp16_ef(uint32_t s, const void* g) {
    asm volatile(
        "{\n\t.reg .b64 pol;\n\t"
        "createpolicy.fractional.L2::evict_first.b64 pol;\n\t"
        "cp.async.cg.shared.global.L2::cache_hint [%0], [%1], 16, pol;\n\t}"
        :: "r"(s), "l"(g));
}
__device__ __forceinline__ void ldsm_x4(uint32_t& r0, uint32_t& r1,
                                        uint32_t& r2, uint32_t& r3, uint32_t addr) {
    asm volatile("ldmatrix.sync.aligned.m8n8.x4.shared.b16 {%0,%1,%2,%3}, [%4];"
                 : "=r"(r0), "=r"(r1), "=r"(r2), "=r"(r3) : "r"(addr));
}
__device__ __forceinline__ void mma16816(float* c, const uint32_t* a,
                                         uint32_t b0, uint32_t b1) {
    asm volatile("mma.sync.aligned.m16n8k16.row.col.f32.f16.f16.f32 "
                 "{%0,%1,%2,%3}, {%4,%5,%6,%7}, {%8,%9}, {%0,%1,%2,%3};"
                 : "+f"(c[0]), "+f"(c[1]), "+f"(c[2]), "+f"(c[3])
                 : "r"(a[0]), "r"(a[1]), "r"(a[2]), "r"(a[3]), "r"(b0), "r"(b1));
}
// PDL primitives (sm_90+)
__device__ __forceinline__ void pdl_trigger() {
    asm volatile("griddepcontrol.launch_dependents;");
}
__device__ __forceinline__ void pdl_wait() {
    asm volatile("griddepcontrol.wait;");
}

__device__ __forceinline__ void bfly4(float4& a, float4& b) {
    float4 ta = a, tb = b;
    a.x = ta.x + tb.x; a.y = ta.y + tb.y; a.z = ta.z + tb.z; a.w = ta.w + tb.w;
    b.x = ta.x - tb.x; b.y = ta.y - tb.y; b.z = ta.z - tb.z; b.w = ta.w - tb.w;
}
__device__ __forceinline__ void wht8(float4* v) {
#pragma unroll
    for (int s = 1; s < 8; s <<= 1)
#pragma unroll
        for (int e = 0; e < 8; e++)
            if ((e & s) == 0) bfly4(v[e], v[e | s]);
}
__device__ __forceinline__ void wht4(float4* v) {
#pragma unroll
    for (int s = 1; s < 4; s <<= 1)
#pragma unroll
        for (int e = 0; e < 4; e++)
            if ((e & s) == 0) bfly4(v[e], v[e | s]);
}

// ---------------------------------------------------------------------------
// K0: decode packed ternary weights -> fp16 g_wf16.
// ---------------------------------------------------------------------------
__global__ void __launch_bounds__(256) k0_decode(const int* __restrict__ wpk) {
    const int g    = blockIdx.x;
    const int cb   = blockIdx.y * 2;
    const int o    = threadIdx.x >> 1;
    const int half = threadIdx.x & 1;
    const int* row32 = wpk + ((size_t)g * 128 + o) * 32 + half * 16;
    uint2* dst = (uint2*)(g_wf16 + ((size_t)(g * 128 + o)) * 64 + half * 32);
#pragma unroll
    for (int cc = 0; cc < 2; cc++) {
        int c = cb + cc;
        uint32_t by = (uint32_t)__ldg(row32 + c) & 0xFFu;
        uint32_t bits[4];
#pragma unroll
        for (int j = 0; j < 4; j++) {
            uint32_t v2 = (by >> (6 - 2 * j)) & 3u;
            bits[j] = (v2 == 1u) ? 0u : ((v2 == 2u) ? 0x3C00u : 0xBC00u);
        }
        dst[c] = make_uint2(bits[0] | (bits[1] << 16), bits[2] | (bits[3] << 16));
    }
}

// ---------------------------------------------------------------------------
// K1: stage-1 Hadamard (radix 8x4 via SMEM, float4 lanes). CTA = 2 tokens.
// Ends with PDL trigger so K2 may launch during K1's drain.
// ---------------------------------------------------------------------------
__global__ void __launch_bounds__(256) k1_mix(const float* __restrict__ x) {
    __shared__ float4 su[2 * 4 * 8 * 32];           // 32 KB

    const int tid = threadIdx.x;
    const int tl  = tid >> 7;
    const int r   = tid & 127;
    const int t   = blockIdx.x * 2 + tl;
    const int iq  = r & 31;

    {
        const int g1 = r >> 5;
        const float4* xr = (const float4*)(x + (size_t)t * 4096) + g1 * 256 + iq;
        float4 v[8];
#pragma unroll
        for (int g0 = 0; g0 < 8; g0++) v[g0] = __ldcs(xr + g0 * 32);
        wht8(v);
        float4* dst = su + ((tl * 4 + g1) * 8) * 32 + iq;
#pragma unroll
        for (int h0 = 0; h0 < 8; h0++) dst[h0 * 32] = v[h0];
    }
    __syncthreads();
    {
        const int h0a = r >> 5;
        uint2* xm = (uint2*)g_xm2;
#pragma unroll
        for (int k = 0; k < 2; k++) {
            const int h0 = h0a + k * 4;
            float4 v[4];
#pragma unroll
            for (int g1 = 0; g1 < 4; g1++)
                v[g1] = su[((tl * 4 + g1) * 8 + h0) * 32 + iq];
            wht4(v);
#pragma unroll
            for (int h1 = 0; h1 < 4; h1++) {
                __half2 lo = __floats2half2_rn(v[h1].x, v[h1].y);
                __half2 hi = __floats2half2_rn(v[h1].z, v[h1].w);
                xm[((size_t)(h1 * 8 + h0) * N_TOKENS + t) * 32 + iq] =
                    make_uint2(*(uint32_t*)&lo, *(uint32_t*)&hi);
            }
        }
    }
    pdl_trigger();
}

// ---------------------------------------------------------------------------
// K2: persistent single-wave GEMM (grid (13, 32g) = 416 CTAs, one wave).
// PDL: issues the (K1-independent) B fill, then griddepcontrol.wait before
// touching xm. Ends with trigger for K3.
// ---------------------------------------------------------------------------
#define SMS 272
#define ABUF (64 * SMS)                // 17408
#define BBUF (128 * SMS)               // 34816
#define K2_SMEM (2 * ABUF + BBUF)      // 69632  -> 3 CTAs/SM
#define K2_SLICES 13
#define NTILES 128                     // 64-token tiles total

__global__ void __launch_bounds__(256, 3) k2_gemm() {
    extern __shared__ char smem[];
    const uint32_t sA0 = smem_u32(smem);
    const uint32_t sB  = sA0 + 2 * ABUF;

    const int tid  = threadIdx.x;
    const int wid  = tid >> 5;
    const int lane = tid & 31;
    const int s = blockIdx.x;          // 0..12
    const int g = blockIdx.y;          // 0..31
    const int ntiles = (NTILES - s + K2_SLICES - 1) / K2_SLICES;

    // ---- B fill (independent of K1) — issued before the PDL wait ----
    {
        const char* srcB = (const char*)(g_wf16 + (size_t)g * 128 * 64);
#pragma unroll
        for (int it = 0; it < 8; it++) {
            int idx = tid + it * 256;
            int rr = idx >> 4, q = idx & 15;
            cp16(sB + rr * SMS + q * 16, srcB + (size_t)rr * 256 + q * 16);
        }
    }
    pdl_wait();                        // K1's xm now complete & visible

    const char* xbase = (const char*)(g_xm2 + (size_t)g * N_TOKENS * 64);
    {
        const char* src = xbase + (size_t)s * 64 * 256;
#pragma unroll
        for (int it = 0; it < 4; it++) {
            int idx = tid + it * 256;
            int rr = idx >> 4, q = idx & 15;
            cp16_ef(sA0 + rr * SMS + q * 16, src + (size_t)rr * 256 + q * 16);
        }
    }
    asm volatile("cp.async.commit_group;");

    const int wm = (wid & 1) * 32;
    const int wn = (wid >> 1) * 32;
    const int a_row = (lane & 7) + ((lane >> 3) & 1) * 8;
    const int a_col = ((lane >> 4) & 1) * 16;
    const int b_row = (lane & 7) + ((lane >> 4) & 1) * 8;
    const int b_col = ((lane >> 3) & 1) * 16;
    const uint32_t bLane = sB + (wn + b_row) * SMS + b_col;

    for (int k = 0; k < ntiles; k++) {
        const int tt = s + k * K2_SLICES;
        const uint32_t sAc = sA0 + (uint32_t)(k & 1) * ABUF;

        if (k + 1 < ntiles) {
            const uint32_t sAn = sA0 + (uint32_t)((k + 1) & 1) * ABUF;
            const char* src = xbase + (size_t)(tt + K2_SLICES) * 64 * 256;
#pragma unroll
            for (int it = 0; it < 4; it++) {
                int idx = tid + it * 256;
                int rr = idx >> 4, q = idx & 15;
                cp16_ef(sAn + rr * SMS + q * 16, src + (size_t)rr * 256 + q * 16);
            }
            asm volatile("cp.async.commit_group;");
            asm volatile("cp.async.wait_group 1;");
        } else {
            asm volatile("cp.async.wait_group 0;");
        }
        __syncthreads();

        const uint32_t aLane = sAc + (wm + a_row) * SMS + a_col;
        float acc[2][4][4];
#pragma unroll
        for (int mt = 0; mt < 2; mt++)
#pragma unroll
            for (int nt = 0; nt < 4; nt++)
#pragma unroll
                for (int q = 0; q < 4; q++) acc[mt][nt][q] = 0.0f;

#pragma unroll
        for (int ks = 0; ks < 8; ks++) {
            uint32_t a[2][4];
#pragma unroll
            for (int mt = 0; mt < 2; mt++)
                ldsm_x4(a[mt][0], a[mt][1], a[mt][2], a[mt][3],
                        aLane + mt * 16 * SMS + ks * 32);
            uint32_t b[2][4];
#pragma unroll
            for (int n2 = 0; n2 < 2; n2++)
                ldsm_x4(b[n2][0], b[n2][1], b[n2][2], b[n2][3],
                        bLane + n2 * 16 * SMS + ks * 32);
#pragma unroll
            for (int mt = 0; mt < 2; mt++)
#pragma unroll
                for (int nt = 0; nt < 4; nt++) {
                    uint32_t b0 = b[nt >> 1][(nt & 1) * 2 + 0];
                    uint32_t b1 = b[nt >> 1][(nt & 1) * 2 + 1];
                    mma16816(acc[mt][nt], a[mt], b0, b1);
                }
        }

        __syncthreads();
        {
            const int rbase = wm + (lane >> 2);
#pragma unroll
            for (int mt = 0; mt < 2; mt++) {
#pragma unroll
                for (int nt = 0; nt < 4; nt++) {
                    int colu = (wn >> 1) + nt * 4 + (lane & 3);
                    __half2 lo = __floats2half2_rn(acc[mt][nt][0], acc[mt][nt][1]);
                    __half2 hi = __floats2half2_rn(acc[mt][nt][2], acc[mt][nt][3]);
                    int r0 = rbase + mt * 16;
                    *(uint32_t*)(smem + (sAc - sA0) + (size_t)r0 * SMS + (size_t)colu * 4) = *(uint32_t*)&lo;
                    *(uint32_t*)(smem + (sAc - sA0) + (size_t)(r0 + 8) * SMS + (size_t)colu * 4) = *(uint32_t*)&hi;
                }
            }
        }
        __syncthreads();
        {
            uint32_t* ypbase = g_yp2 + ((size_t)tt * 64 * 32 + g) * 64;
#pragma unroll
            for (int it = 0; it < 4; it++) {
                int idx = tid + it * 256;
                int row = idx >> 4, q = idx & 15;
                uint4 v = *(const uint4*)(smem + (sAc - sA0) + (size_t)row * SMS + (size_t)q * 16);
                *(uint4*)(ypbase + (size_t)row * 2048 + q * 4) = v;
            }
        }
        __syncthreads();
    }
    pdl_trigger();
}

// ---------------------------------------------------------------------------
// K3: stage-3 Hadamard + beta/32 (radix 8x4 via SMEM). CTA = 2 tokens.
// PDL: loads beta (input, K2-independent) before griddepcontrol.wait.
// ---------------------------------------------------------------------------
__global__ void __launch_bounds__(256) k3_mix(const float* __restrict__ beta,
                                              float* __restrict__ y) {
    __shared__ float4 su[2 * 4 * 8 * 32];

    const int tid = threadIdx.x;
    const int tl  = tid >> 7;
    const int r   = tid & 127;
    const int t   = blockIdx.x * 2 + tl;
    const int oq  = r & 31;

    // Independent prologue: beta scales
    const float4 bb = __ldg((const float4*)beta + oq);
    const float s0 = bb.x * (1.0f / 32.0f), s1 = bb.y * (1.0f / 32.0f);
    const float s2 = bb.z * (1.0f / 32.0f), s3 = bb.w * (1.0f / 32.0f);

    pdl_wait();                        // K2's yp now complete & visible

    {
        const int g1 = r >> 5;
        const uint2* yr = (const uint2*)g_yp2 + (size_t)t * 1024 + g1 * 256 + oq;
        float4 v[8];
#pragma unroll
        for (int g0 = 0; g0 < 8; g0++) {
            uint2 pk = __ldcs(yr + g0 * 32);
            float2 a = __half22float2(*(__half2*)&pk.x);
            float2 b = __half22float2(*(__half2*)&pk.y);
            v[g0] = make_float4(a.x, a.y, b.x, b.y);
        }
        wht8(v);
        float4* dst = su + ((tl * 4 + g1) * 8) * 32 + oq;
#pragma unroll
        for (int h0 = 0; h0 < 8; h0++) dst[h0 * 32] = v[h0];
    }
    __syncthreads();
    {
        const int h0a = r >> 5;
        float4* out = (float4*)(y + (size_t)t * 4096) + oq;
#pragma unroll
        for (int k = 0; k < 2; k++) {
            const int h0 = h0a + k * 4;
            float4 v[4];
#pragma unroll
            for (int g1 = 0; g1 < 4; g1++)
                v[g1] = su[((tl * 4 + g1) * 8 + h0) * 32 + oq];
            wht4(v);
#pragma unroll
            for (int h1 = 0; h1 < 4; h1++) {
                float4 o;
                o.x = v[h1].x * s0; o.y = v[h1].y * s1;
                o.z = v[h1].z * s2; o.w = v[h1].w * s3;
                __stcs(out + (h1 * 8 + h0) * 32, o);
            }
        }
    }
}

// ---------------------------------------------------------------------------
// Launch: single stream; K2 and K3 launched with programmatic stream
// serialization (PDL) to overlap their prologues with the predecessor's
// drain. Inputs dispatched BY ELEMENT COUNT (order-proof).
// ---------------------------------------------------------------------------
extern "C" void kernel_launch(void* const* d_in, const int* in_sizes, int n_in,
                              void* d_out, int out_size) {
    const float* x    = nullptr;
    const int*   wp   = nullptr;
    const float* beta = nullptr;

    for (int i = 0; i < n_in; i++) {
        switch (in_sizes[i]) {
            case 33554432: x    = (const float*)d_in[i]; break;
            case 131072:   wp   = (const int*)d_in[i];   break;
            case 128:      beta = (const float*)d_in[i]; break;
            default: break;   // H (1024) ignored
        }
    }
    if (!x)    x    = (const float*)d_in[0];
    if (!wp)   wp   = (const int*)d_in[1];
    if (!beta) beta = (const float*)d_in[2];

    float* y = (float*)d_out;

    cudaFuncSetAttribute(k2_gemm, cudaFuncAttributeMaxDynamicSharedMemorySize, K2_SMEM);

    k0_decode<<<dim3(NGROUP, 8), 256>>>(wp);
    k1_mix<<<N_TOKENS / 2, 256>>>(x);

    cudaLaunchAttribute pdl[1];
    pdl[0].id = cudaLaunchAttributeProgrammaticStreamSerialization;
    pdl[0].val.programmaticStreamSerializationAllowed = 1;

    {   // K2 with PDL
        cudaLaunchConfig_t cfg = {};
        cfg.gridDim = dim3(K2_SLICES, NGROUP);
        cfg.blockDim = dim3(256);
        cfg.dynamicSmemBytes = K2_SMEM;
        cfg.stream = 0;
        cfg.attrs = pdl;
        cfg.numAttrs = 1;
        cudaLaunchKernelEx(&cfg, k2_gemm);
    }
    {   // K3 with PDL
        cudaLaunchConfig_t cfg = {};
        cfg.gridDim = dim3(N_TOKENS / 2);
        cfg.blockDim = dim3(256);
        cfg.dynamicSmemBytes = 0;
        cfg.stream = 0;
        cfg.attrs = pdl;
        cfg.numAttrs = 1;
        cudaLaunchKernelEx(&cfg, k3_mix, beta, y);
    }
}